// round 16
// baseline (speedup 1.0000x reference)
#include <cuda_runtime.h>
#include <cuda_fp16.h>
#include <math.h>

#define NB 2
#define NV 180
#define NR 32
#define NC 512
#define NPIX 512
#define PI_D 3.14159265358979323846

#define NRP (NR / 2)
#define NKGT (NRP / 2)   // 8 kg-groups per (b,v)

// Filtered sinogram, PAIR-INTERLEAVED uint (half2) layout:
//   pairIdx = (b*NV+v)*NRP + rp ; kg = pairIdx>>1 ; sub = pairIdx&1
//   g_pack2[kg*2*NC + 2*i + sub] = half2( filt[2rp_img0, i], filt[2rp_img1, i] )
// As uint2: g2[kg*NC + i] = ( pairEven@i , pairOdd@i )  -> 8B-aligned LDG.64.
// +64 pad: staging reads overrun a row by <=2 uint2 (weight-0, zero-init).
__device__ unsigned g_pack2[NB * NV * NRP * NC + 64];

// One block filters FOUR consecutive real rows as TWO packed complex 512-pt
// FFTs. DIF forward -> ramp in bitrev slots -> DIT inverse (conj twiddles).
__global__ void __launch_bounds__(256) filter_kernel(const float* __restrict__ sino) {
    __shared__ float sre[1024];   // [f*512 + i]
    __shared__ float sim[1024];
    __shared__ float twr[256];
    __shared__ float twi[256];

    int tid = threadIdx.x;
    int base = blockIdx.x * 4 * NC;   // 4 rows per block

    {
        float s, c;
        sincospif(-(float)tid * (1.0f / 256.0f), &s, &c);  // exp(-2*pi*i*tid/512)
        twr[tid] = c;
        twi[tid] = s;
    }
    sre[tid]             = sino[base + tid];
    sre[tid + 256]       = sino[base + tid + 256];
    sim[tid]             = sino[base + NC + tid];
    sim[tid + 256]       = sino[base + NC + tid + 256];
    sre[512 + tid]       = sino[base + 2 * NC + tid];
    sre[512 + tid + 256] = sino[base + 2 * NC + tid + 256];
    sim[512 + tid]       = sino[base + 3 * NC + tid];
    sim[512 + tid + 256] = sino[base + 3 * NC + tid + 256];
    __syncthreads();

    // ---- DIF forward ----
    {
        int step = 1;
        for (int len = 512; len >= 2; len >>= 1, step <<= 1) {
            int half = len >> 1;
            int grp = tid / half;
            int j = tid - grp * half;
            int i0 = grp * len + j;
            int i1 = i0 + half;
            int tj = j * step;
            float wr = twr[tj], wi = twi[tj];
            #pragma unroll
            for (int f = 0; f < 2; ++f) {
                int o = f << 9;
                float ar = sre[o + i0], ai = sim[o + i0];
                float br = sre[o + i1], bi = sim[o + i1];
                sre[o + i0] = ar + br;
                sim[o + i0] = ai + bi;
                float dr = ar - br, di = ai - bi;
                sre[o + i1] = dr * wr - di * wi;
                sim[o + i1] = dr * wi + di * wr;
            }
            if (len >= 128) __syncthreads();
            else __syncwarp();
        }
    }

    // ---- ramp multiply in bitrev slots (warp-local elements 2t, 2t+1) ----
    #pragma unroll
    for (int q = 0; q < 2; ++q) {
        int n = 2 * tid + q;
        int fb = (int)(__brev((unsigned)n) >> 23);
        int m = min(fb, 512 - fb);
        float scale = (float)m * (2.0f / (512.0f * 512.0f));
        #pragma unroll
        for (int f = 0; f < 2; ++f) {
            int o = f << 9;
            sre[o + n] *= scale;
            sim[o + n] *= scale;
        }
    }
    __syncwarp();

    // ---- DIT inverse (conj twiddles) ----
    {
        int step = 256;
        for (int len = 2; len <= 512; len <<= 1, step >>= 1) {
            int half = len >> 1;
            int grp = tid / half;
            int j = tid - grp * half;
            int i0 = grp * len + j;
            int i1 = i0 + half;
            int tj = j * step;
            float wr = twr[tj], wi = -twi[tj];
            #pragma unroll
            for (int f = 0; f < 2; ++f) {
                int o = f << 9;
                float ar = sre[o + i0], ai = sim[o + i0];
                float br = sre[o + i1], bi = sim[o + i1];
                float vr = br * wr - bi * wi;
                float vi = br * wi + bi * wr;
                sre[o + i0] = ar + vr;
                sim[o + i0] = ai + vi;
                sre[o + i1] = ar - vr;
                sim[o + i1] = ai - vi;
            }
            if (len >= 64) __syncthreads();
            else __syncwarp();
        }
    }

    // pair p = 2*blockIdx.x + f  ->  kg = blockIdx.x, sub = f
    // g_pack2[blockIdx.x*2*NC + 2*i + f]
    unsigned* outp = g_pack2 + blockIdx.x * 2 * NC;
    #pragma unroll
    for (int f = 0; f < 2; ++f) {
        int o = f << 9;
        __half2 h0 = __floats2half2_rn(sre[o + tid], sim[o + tid]);
        __half2 h1 = __floats2half2_rn(sre[o + tid + 256], sim[o + tid + 256]);
        outp[2 * tid + f]         = *(unsigned*)&h0;
        outp[2 * (tid + 256) + f] = *(unsigned*)&h1;
    }
}

#define TILE  32
#define WIN   52
#define NPAIR 8            // 8 image-pairs = 16 images per block
#define NKG   (NPAIR / 2)  // 4 pair-groups of 2 pairs
#define NBUF  4            // ring buffers (stage distance 2)

// sp[buf][view][loc][kg] : uint4 = (pairA.lo, pairA.hi, pairB.lo, pairB.hi).
// Per-loc stride padded to 5 uint4 (80B) -> bank stride 20 mod 32.
__global__ void __launch_bounds__(256, 2) backproj_kernel(float* __restrict__ out) {
    __shared__ uint4 sp[NBUF][2][WIN][NKG + 1];
    __shared__ float scos[NV];
    __shared__ float ssin[NV];
    __shared__ int   swin[NV];

    int tid = threadIdx.x;   // 0..255 (1-D launch)

    int g    = blockIdx.z;      // 0..3
    int b    = g >> 1;
    int rblk = g & 1;
    int r0   = rblk * (2 * NPAIR);
    int rp0  = rblk * NPAIR;
    int x0   = blockIdx.x * TILE;
    int y0   = blockIdx.y * TILE;

    float xt = (float)x0 - 255.5f;
    float yt = (float)y0 - 255.5f;

    // Precompute per-view cos/sin + staged-window start (block-uniform).
    if (tid < NV) {
        float s, c;
        sincospif((float)tid * (1.0f / (float)NV), &s, &c);
        scos[tid] = c;
        ssin[tid] = s;
        float tmin = xt * c + yt * s + 255.5f
                   + fminf(31.0f * c, 0.0f) + fminf(31.0f * s, 0.0f);
        int wv = (int)floorf(tmin) - 1;
        swin[tid] = max(0, min(wv, 465));
    }

    // 8x4 warp footprint: warps tiled 2 wide x 4 tall over the 16x16 grid
    int lane = tid & 31;
    int w    = tid >> 5;
    int tx = ((w & 1) << 3) | (lane & 7);   // 0..15
    int ty = ((w >> 1) << 2) | (lane >> 3); // 0..15

    float xb = (float)(x0 + tx) - 255.5f;
    float yb = (float)(y0 + ty) - 255.5f;

    // staging: 208 slots (kg, off); each thread handles both views of one slot
    int skg  = tid / WIN;            // 0..4 (valid < 4)
    int soff = tid - skg * WIN;
    bool stager = (tid < NKG * WIN);

    const uint2* g2 = (const uint2*)g_pack2;
    // kg-row base: (b*NV + v)*NKGT + rp0/2 + skg
    int kgrow0 = (b * NV) * NKGT + (rp0 >> 1) + skg;

    unsigned long long acc[2][2][NPAIR];
    #pragma unroll
    for (int py = 0; py < 2; ++py)
        #pragma unroll
        for (int px = 0; px < 2; ++px)
            #pragma unroll
            for (int k = 0; k < NPAIR; ++k)
                acc[py][px][k] = 0ull;

    const __half2 ones2 = __floats2half2_rn(1.0f, 1.0f);

    __syncthreads();   // tables ready (also makes swin visible to stagers)

    // stage views v, v+1 into ring buffer bi (windows from swin[])
    // 2 coalesced LDG.64 per view: g2[row + gi], g2[row + gi+1]
    auto stage = [&](int bi, int v) {
        if (!stager) return;
        {
            int row = (kgrow0 + v * NKGT) * NC;
            int gi = swin[v] + soff;
            uint2 u0 = g2[row + gi];
            uint2 u1 = g2[row + gi + 1];
            sp[bi][0][soff][skg] = make_uint4(u0.x, u1.x, u0.y, u1.y);
        }
        {
            int row = (kgrow0 + (v + 1) * NKGT) * NC;
            int gi = swin[v + 1] + soff;
            uint2 u0 = g2[row + gi];
            uint2 u1 = g2[row + gi + 1];
            sp[bi][1][soff][skg] = make_uint4(u0.x, u1.x, u0.y, u1.y);
        }
    };

    // prologue: stage iterations 0 and 1
    stage(0, 0);
    stage(1, 2);
    __syncthreads();

    for (int it = 0; it < NV / 2; ++it) {
        int buf = it & (NBUF - 1);

        if (it + 2 < NV / 2)
            stage((it + 2) & (NBUF - 1), 2 * it + 4);

        int v = 2 * it;
        float c0 = scos[v],     s0 = ssin[v];
        float c1 = scos[v + 1], s1 = ssin[v + 1];
        int   w0 = swin[v],     w1 = swin[v + 1];

        float t000 = fmaf(xb, c0, fmaf(yb, s0, 255.5f));
        float t001 = fmaf(xb, c1, fmaf(yb, s1, 255.5f));
        float c160 = 16.0f * c0, s160 = 16.0f * s0;
        float c161 = 16.0f * c1, s161 = 16.0f * s1;

        #pragma unroll
        for (int py = 0; py < 2; ++py) {
            #pragma unroll
            for (int px = 0; px < 2; ++px) {
                float ta = t000 + (float)px * c160 + (float)py * s160;
                ta = fminf(fmaxf(ta, 0.0f), 511.0f);
                int ia = __float2int_rd(ta);
                float wa = ta - (float)ia;
                int la = ia - w0;
                __half2 wab  = __float2half2_rn(wa);
                __half2 wab1 = __hsub2(ones2, wab);

                float tb = t001 + (float)px * c161 + (float)py * s161;
                tb = fminf(fmaxf(tb, 0.0f), 511.0f);
                int ib = __float2int_rd(tb);
                float wb = tb - (float)ib;
                int lb = ib - w1;
                __half2 wbb  = __float2half2_rn(wb);
                __half2 wbb1 = __hsub2(ones2, wbb);

                // hoist all 8 loads (both views x 4 kg) -> deep MLP
                uint4 qa[NKG], qb[NKG];
                #pragma unroll
                for (int kg = 0; kg < NKG; ++kg) qa[kg] = sp[buf][0][la][kg];
                #pragma unroll
                for (int kg = 0; kg < NKG; ++kg) qb[kg] = sp[buf][1][lb][kg];

                #pragma unroll
                for (int kg = 0; kg < NKG; ++kg) {
                    // pair A = 2*kg
                    __half2 vA;
                    vA = __hmul2(*(__half2*)&qa[kg].x, wab1);
                    vA = __hfma2(*(__half2*)&qa[kg].y, wab, vA);
                    vA = __hfma2(*(__half2*)&qb[kg].x, wbb1, vA);
                    vA = __hfma2(*(__half2*)&qb[kg].y, wbb, vA);
                    float2 fA = __half22float2(vA);
                    unsigned long long vpA;
                    asm("mov.b64 %0, {%1, %2};" : "=l"(vpA) : "f"(fA.x), "f"(fA.y));
                    asm("add.rn.f32x2 %0, %0, %1;" : "+l"(acc[py][px][2 * kg]) : "l"(vpA));
                    // pair B = 2*kg+1
                    __half2 vB;
                    vB = __hmul2(*(__half2*)&qa[kg].z, wab1);
                    vB = __hfma2(*(__half2*)&qa[kg].w, wab, vB);
                    vB = __hfma2(*(__half2*)&qb[kg].z, wbb1, vB);
                    vB = __hfma2(*(__half2*)&qb[kg].w, wbb, vB);
                    float2 fB = __half22float2(vB);
                    unsigned long long vpB;
                    asm("mov.b64 %0, {%1, %2};" : "=l"(vpB) : "f"(fB.x), "f"(fB.y));
                    asm("add.rn.f32x2 %0, %0, %1;" : "+l"(acc[py][px][2 * kg + 1]) : "l"(vpB));
                }
            }
        }

        __syncthreads();
    }

    const float outscale = (float)(PI_D / (double)NV);
    #pragma unroll
    for (int k = 0; k < NPAIR; ++k) {
        #pragma unroll
        for (int py = 0; py < 2; ++py) {
            #pragma unroll
            for (int px = 0; px < 2; ++px) {
                int y = y0 + ty + py * 16;
                int x = x0 + tx + px * 16;
                int imgA = r0 + 2 * k;
                float ax, ay;
                asm("mov.b64 {%0, %1}, %2;" : "=f"(ax), "=f"(ay) : "l"(acc[py][px][k]));
                float va = fmaxf(ax * outscale, 0.0f);
                float vb = fmaxf(ay * outscale, 0.0f);
                out[(((b * NR + imgA) * NPIX) + y) * NPIX + x] = va;
                out[(((b * NR + imgA + 1) * NPIX) + y) * NPIX + x] = vb;
            }
        }
    }
}

extern "C" void kernel_launch(void* const* d_in, const int* in_sizes, int n_in,
                              void* d_out, int out_size) {
    const float* sino = (const float*)d_in[0];
    float* out = (float*)d_out;
    (void)in_sizes; (void)n_in; (void)out_size;

    filter_kernel<<<NB * NV * NR / 4, 256>>>(sino);   // 4 rows (2 FFTs) per block
    dim3 bpGrid(NPIX / TILE, NPIX / TILE, (NB * NR) / (2 * NPAIR));
    backproj_kernel<<<bpGrid, 256>>>(out);   // 1-D 256-thread block
}